// round 1
// baseline (speedup 1.0000x reference)
#include <cuda_runtime.h>

// SSIM loss, separable Gaussian 11x11, fields {s,d,s^2,d^2} with s=x+y, d=x-y.
// Column-strip kernel: each block owns a 64-wide x 512-tall strip of one plane.
// Ring buffer (32 rows) of horizontal-conv results in shared memory.

namespace {
constexpr int WI = 512, HI = 512;
constexpr int SW = 64;            // strip width
constexpr int CH = 16;            // rows per batch / output chunk
constexpr int NCHUNK = HI / CH;   // 32
constexpr int STG_W = 84;         // staging row stride in floats (80 used)
constexpr int RING_W = 68;        // ring row stride in floats (64 used)
constexpr float C1 = 1e-4f;       // 0.01^2
constexpr float C2 = 9e-4f;       // 0.03^2
constexpr double NPIX = 25165824.0; // 32*3*512*512
}

__device__ double g_accum;

__global__ void ssim_zero_k() { g_accum = 0.0; }

__global__ void __launch_bounds__(256) ssim_main(const float* __restrict__ img1,
                                                 const float* __restrict__ img2)
{
    __shared__ float Sst[CH][STG_W];
    __shared__ float Dst[CH][STG_W];
    __shared__ float Ring[4][32][RING_W];
    __shared__ float wsum[8];

    const float Wt[11] = {0.00102838f, 0.00759877f, 0.03600077f, 0.10936070f,
                          0.21300552f, 0.26601174f, 0.21300552f, 0.10936070f,
                          0.03600077f, 0.00759877f, 0.00102838f};

    const int tid = threadIdx.x;
    const int plane = blockIdx.y;          // 0..95  (B*C planes)
    const int x0 = blockIdx.x * SW;        // strip origin
    const float* p1 = img1 + (size_t)plane * (size_t)(WI * HI);
    const float* p2 = img2 + (size_t)plane * (size_t)(WI * HI);

    // horizontal-pass mapping: 16 rows x 16 col-groups (4 outputs each)
    const int hrow = tid >> 4;
    const int hcg  = tid & 15;
    // vertical-pass mapping: 64 cols x 4 row-groups (4 output rows each)
    const int vx  = tid & 63;
    const int vrg = tid >> 6;

    float acc = 0.f;

    auto produce = [&](int p) {
        const int yBase = p * CH - 5;      // rows 16p-5 .. 16p+10
        // ---- stage 16 rows x 80 cols of s,d (zero-padded outside image) ----
        #pragma unroll
        for (int u0 = 0; u0 < 2; u0++) {
            int u = tid + u0 * 256;
            if (u < CH * 20) {
                int r  = u / 20;
                int c4 = u - r * 20;
                int yy = yBase + r;
                int gx = x0 - 8 + c4 * 4;
                float4 a = make_float4(0.f, 0.f, 0.f, 0.f);
                float4 b = make_float4(0.f, 0.f, 0.f, 0.f);
                if ((unsigned)yy < (unsigned)HI && (unsigned)gx < (unsigned)WI) {
                    a = *reinterpret_cast<const float4*>(p1 + (size_t)yy * WI + gx);
                    b = *reinterpret_cast<const float4*>(p2 + (size_t)yy * WI + gx);
                }
                float4 s = make_float4(a.x + b.x, a.y + b.y, a.z + b.z, a.w + b.w);
                float4 d = make_float4(a.x - b.x, a.y - b.y, a.z - b.z, a.w - b.w);
                *reinterpret_cast<float4*>(&Sst[r][c4 * 4]) = s;
                *reinterpret_cast<float4*>(&Dst[r][c4 * 4]) = d;
            }
        }
        __syncthreads();
        // ---- horizontal conv of 4 fields into ring ----
        {
            const int yy = yBase + hrow;
            const int slot = yy & 31;
            float hs[4]  = {0.f, 0.f, 0.f, 0.f};
            float hd[4]  = {0.f, 0.f, 0.f, 0.f};
            float hs2[4] = {0.f, 0.f, 0.f, 0.f};
            float hd2[4] = {0.f, 0.f, 0.f, 0.f};
            #pragma unroll
            for (int b4 = 0; b4 < 5; b4++) {
                float4 sv4 = *reinterpret_cast<const float4*>(&Sst[hrow][(hcg + b4) * 4]);
                float4 dv4 = *reinterpret_cast<const float4*>(&Dst[hrow][(hcg + b4) * 4]);
                const float svv[4] = {sv4.x, sv4.y, sv4.z, sv4.w};
                const float dvv[4] = {dv4.x, dv4.y, dv4.z, dv4.w};
                #pragma unroll
                for (int e = 0; e < 4; e++) {
                    const int j = b4 * 4 + e;
                    const float s  = svv[e], d = dvv[e];
                    const float s2 = s * s,  d2 = d * d;
                    #pragma unroll
                    for (int o = 0; o < 4; o++) {
                        if (j >= o + 3 && j <= o + 13) {
                            const float w = Wt[j - o - 3];
                            hs[o]  += w * s;
                            hd[o]  += w * d;
                            hs2[o] += w * s2;
                            hd2[o] += w * d2;
                        }
                    }
                }
            }
            *reinterpret_cast<float4*>(&Ring[0][slot][hcg * 4]) = make_float4(hs[0],  hs[1],  hs[2],  hs[3]);
            *reinterpret_cast<float4*>(&Ring[1][slot][hcg * 4]) = make_float4(hd[0],  hd[1],  hd[2],  hd[3]);
            *reinterpret_cast<float4*>(&Ring[2][slot][hcg * 4]) = make_float4(hs2[0], hs2[1], hs2[2], hs2[3]);
            *reinterpret_cast<float4*>(&Ring[3][slot][hcg * 4]) = make_float4(hd2[0], hd2[1], hd2[2], hd2[3]);
        }
        __syncthreads();
    };

    produce(0);
    for (int k = 0; k < NCHUNK; k++) {
        produce(k + 1);   // makes intermediate rows 16k+11 .. 16k+26 available

        // ---- vertical conv + SSIM for output rows [16k, 16k+16) ----
        const int yo0 = k * CH + vrg * 4;  // first of 4 output rows for this thread
        float aS[4]  = {0.f, 0.f, 0.f, 0.f};
        float aD[4]  = {0.f, 0.f, 0.f, 0.f};
        float aS2[4] = {0.f, 0.f, 0.f, 0.f};
        float aD2[4] = {0.f, 0.f, 0.f, 0.f};
        #pragma unroll
        for (int r = 0; r < 14; r++) {
            const int slot = (yo0 - 5 + r) & 31;
            const float v0 = Ring[0][slot][vx];
            const float v1 = Ring[1][slot][vx];
            const float v2 = Ring[2][slot][vx];
            const float v3 = Ring[3][slot][vx];
            #pragma unroll
            for (int o = 0; o < 4; o++) {
                if (r >= o && r <= o + 10) {
                    const float w = Wt[r - o];
                    aS[o]  += w * v0;
                    aD[o]  += w * v1;
                    aS2[o] += w * v2;
                    aD2[o] += w * v3;
                }
            }
        }
        #pragma unroll
        for (int o = 0; o < 4; o++) {
            const float mus = aS[o], mud = aD[o], es = aS2[o], ed = aD2[o];
            const float mus_sq = mus * mus, mud_sq = mud * mud;
            const float mu12  = 0.25f * (mus_sq - mud_sq);  // mu1*mu2
            const float musum = 0.5f  * (mus_sq + mud_sq);  // mu1^2+mu2^2
            const float cross = 0.25f * (es - ed);          // conv(x*y)
            const float sqsum = 0.5f  * (es + ed);          // conv(x^2)+conv(y^2)
            const float sigma12 = cross - mu12;
            const float sigsum  = sqsum - musum;            // sigma1^2+sigma2^2
            const float num = (2.f * mu12 + C1) * (2.f * sigma12 + C2);
            const float den = (musum + C1) * (sigsum + C2);
            acc += __fdividef(num, den);
        }
    }

    // ---- block reduction -> one double atomic per block ----
    #pragma unroll
    for (int off = 16; off > 0; off >>= 1)
        acc += __shfl_down_sync(0xffffffffu, acc, off);
    if ((tid & 31) == 0) wsum[tid >> 5] = acc;
    __syncthreads();
    if (tid == 0) {
        float s = 0.f;
        #pragma unroll
        for (int i = 0; i < 8; i++) s += wsum[i];
        atomicAdd(&g_accum, (double)s);
    }
}

__global__ void ssim_final(float* out) {
    out[0] = (float)(1.0 - g_accum * (1.0 / NPIX));
}

extern "C" void kernel_launch(void* const* d_in, const int* in_sizes, int n_in,
                              void* d_out, int out_size) {
    (void)in_sizes; (void)n_in; (void)out_size;
    const float* img1 = (const float*)d_in[0];
    const float* img2 = (const float*)d_in[1];
    ssim_zero_k<<<1, 1>>>();
    ssim_main<<<dim3(WI / SW, 96), 256>>>(img1, img2);
    ssim_final<<<1, 1>>>((float*)d_out);
}

// round 2
// speedup vs baseline: 1.1598x; 1.1598x over previous
#include <cuda_runtime.h>

// SSIM loss, separable Gaussian 11x11 on fields {s,d,s^2,d^2}, s=x+y, d=x-y.
// Single self-finalizing kernel. Packed f32x2 math, AoS float4 ring buffer.

namespace {
constexpr int WI = 512, HI = 512;
constexpr int SW = 64;              // strip width
constexpr int CH = 16;              // rows per produce chunk
constexpr int SEG = 64;             // output rows per block
constexpr int NCH = SEG / CH;       // 4 chunks per block
constexpr int STG2 = 84;            // SD staging row stride (u64/px units, 80 used)
constexpr int RW4 = 66;             // ring row stride in float4 (64 used)
constexpr float C1 = 1e-4f;
constexpr float C2 = 9e-4f;
constexpr double NPIX = 25165824.0; // 32*3*512*512
constexpr unsigned NBLK = 8 * 8 * 96; // 6144 blocks
}

__device__ double g_accum;          // zero-init; reset by last block each launch
__device__ unsigned g_done;

using u64 = unsigned long long;

__device__ __forceinline__ u64 pk(float a, float b) {
    u64 r; asm("mov.b64 %0, {%1, %2};" : "=l"(r) : "f"(a), "f"(b)); return r;
}
__device__ __forceinline__ void upk(float& a, float& b, u64 v) {
    asm("mov.b64 {%0, %1}, %2;" : "=f"(a), "=f"(b) : "l"(v));
}
__device__ __forceinline__ u64 ffma2(u64 a, u64 b, u64 c) {
    u64 d; asm("fma.rn.f32x2 %0, %1, %2, %3;" : "=l"(d) : "l"(a), "l"(b), "l"(c));
    return d;
}
__device__ __forceinline__ u64 fmul2(u64 a, u64 b) {
    u64 d; asm("mul.rn.f32x2 %0, %1, %2;" : "=l"(d) : "l"(a), "l"(b));
    return d;
}

// bank swizzles
__device__ __forceinline__ int SWZ2(int c) { return c ^ ((((c) >> 4) & 1) << 1); } // u64 units
__device__ __forceinline__ int SWZ4(int c) { return c ^ (((c) >> 3) & 7); }        // float4 units

__global__ void __launch_bounds__(256) ssim_main(const float* __restrict__ img1,
                                                 const float* __restrict__ img2,
                                                 float* __restrict__ out)
{
    __shared__ u64 SD[CH][STG2];         // (s,d) packed per px, 10.75 KB
    __shared__ float4 Ring[32][RW4];     // {S,D,S2,D2} per px, 33 KB
    __shared__ float wsum[8];

    const float Wf[6] = {0.00102838f, 0.00759877f, 0.03600077f,
                         0.10936070f, 0.21300552f, 0.26601174f};
    u64 wp[6];
    #pragma unroll
    for (int i = 0; i < 6; i++) wp[i] = pk(Wf[i], Wf[i]);

    const int tid   = threadIdx.x;
    const int x0    = blockIdx.x * SW;
    const int segY  = blockIdx.y * SEG;
    const int plane = blockIdx.z;
    const float* p1 = img1 + (size_t)plane * (size_t)(WI * HI);
    const float* p2 = img2 + (size_t)plane * (size_t)(WI * HI);

    const int hrow = tid >> 4;           // 0..15
    const int hcg  = tid & 15;           // 0..15 (4 outputs each)
    const int vx   = tid & 63;           // 0..63
    const int vrg  = tid >> 6;           // 0..3  (4 output rows each)
    const int vswz = SWZ4(vx);

    float acc = 0.f;

    auto produce = [&](int p) {
        const int yBase = segY + p * CH - 5;
        // ---- stage 16 rows x 80 px of (s,d), zero-padded ----
        #pragma unroll
        for (int u0 = 0; u0 < 2; u0++) {
            int u = tid + u0 * 256;
            if (u < CH * 20) {
                int r  = u / 20;
                int c4 = u - r * 20;
                int yy = yBase + r;
                int gx = x0 - 8 + c4 * 4;
                float4 a = make_float4(0.f, 0.f, 0.f, 0.f);
                float4 b = make_float4(0.f, 0.f, 0.f, 0.f);
                if ((unsigned)yy < (unsigned)HI && (unsigned)gx < (unsigned)WI) {
                    a = *reinterpret_cast<const float4*>(p1 + (size_t)yy * WI + gx);
                    b = *reinterpret_cast<const float4*>(p2 + (size_t)yy * WI + gx);
                }
                ulonglong2 s0, s1;
                s0.x = pk(a.x + b.x, a.x - b.x);
                s0.y = pk(a.y + b.y, a.y - b.y);
                s1.x = pk(a.z + b.z, a.z - b.z);
                s1.y = pk(a.w + b.w, a.w - b.w);
                int c = c4 * 4;
                *reinterpret_cast<ulonglong2*>(&SD[r][SWZ2(c)])     = s0;
                *reinterpret_cast<ulonglong2*>(&SD[r][SWZ2(c + 2)]) = s1;
            }
        }
        __syncthreads();
        // ---- horizontal conv (packed) into ring ----
        {
            const int yy   = yBase + hrow;
            const int slot = yy & 31;
            u64 aSD[4] = {0ull, 0ull, 0ull, 0ull};
            u64 aSQ[4] = {0ull, 0ull, 0ull, 0ull};
            #pragma unroll
            for (int b = 0; b < 10; b++) {
                ulonglong2 v = *reinterpret_cast<const ulonglong2*>(
                    &SD[hrow][SWZ2(hcg * 4 + 2 * b)]);
                #pragma unroll
                for (int e = 0; e < 2; e++) {
                    const int q = 2 * b + e;
                    const u64 sd = (e == 0) ? v.x : v.y;
                    const u64 sq = fmul2(sd, sd);
                    #pragma unroll
                    for (int o = 0; o < 4; o++) {
                        if (q >= o + 3 && q <= o + 13) {
                            const int t = q - o - 3;
                            const int m = (t < 6) ? t : 10 - t;
                            aSD[o] = ffma2(sd, wp[m], aSD[o]);
                            aSQ[o] = ffma2(sq, wp[m], aSQ[o]);
                        }
                    }
                }
            }
            #pragma unroll
            for (int o = 0; o < 4; o++) {
                ulonglong2 st; st.x = aSD[o]; st.y = aSQ[o];
                *reinterpret_cast<ulonglong2*>(&Ring[slot][SWZ4(hcg * 4 + o)]) = st;
            }
        }
        __syncthreads();
    };

    produce(0);
    #pragma unroll 1
    for (int k = 0; k < NCH; k++) {
        produce(k + 1);

        // ---- vertical conv (packed) + SSIM for rows [segY+16k, +16) ----
        const int yo0 = segY + k * CH + vrg * 4;
        u64 aSD[4] = {0ull, 0ull, 0ull, 0ull};
        u64 aSQ[4] = {0ull, 0ull, 0ull, 0ull};
        #pragma unroll
        for (int r = 0; r < 14; r++) {
            const int slot = (yo0 - 5 + r) & 31;
            ulonglong2 v = *reinterpret_cast<const ulonglong2*>(&Ring[slot][vswz]);
            #pragma unroll
            for (int o = 0; o < 4; o++) {
                if (r >= o && r <= o + 10) {
                    const int t = r - o;
                    const int m = (t < 6) ? t : 10 - t;
                    aSD[o] = ffma2(v.x, wp[m], aSD[o]);
                    aSQ[o] = ffma2(v.y, wp[m], aSQ[o]);
                }
            }
        }
        #pragma unroll
        for (int o = 0; o < 4; o++) {
            float mus, mud, es, ed;
            upk(mus, mud, aSD[o]);
            upk(es, ed, aSQ[o]);
            const float mus_sq = mus * mus, mud_sq = mud * mud;
            const float mu12  = 0.25f * (mus_sq - mud_sq);   // mu1*mu2
            const float musum = 0.5f  * (mus_sq + mud_sq);   // mu1^2+mu2^2
            const float cross = 0.25f * (es - ed);           // conv(x*y)
            const float sqsum = 0.5f  * (es + ed);           // conv(x^2)+conv(y^2)
            const float sigma12 = cross - mu12;
            const float sigsum  = sqsum - musum;
            const float num = (2.f * mu12 + C1) * (2.f * sigma12 + C2);
            const float den = (musum + C1) * (sigsum + C2);
            acc += __fdividef(num, den);
        }
    }

    // ---- block reduction -> one double atomic per block ----
    #pragma unroll
    for (int off = 16; off > 0; off >>= 1)
        acc += __shfl_down_sync(0xffffffffu, acc, off);
    if ((tid & 31) == 0) wsum[tid >> 5] = acc;
    __syncthreads();
    if (tid == 0) {
        float s = 0.f;
        #pragma unroll
        for (int i = 0; i < 8; i++) s += wsum[i];
        atomicAdd(&g_accum, (double)s);
        __threadfence();
        unsigned t = atomicAdd(&g_done, 1u);
        if (t == NBLK - 1) {
            double tot = atomicAdd(&g_accum, 0.0);   // L2-coherent read
            out[0] = (float)(1.0 - tot * (1.0 / NPIX));
            g_accum = 0.0;                            // reset for next launch
            g_done  = 0u;
        }
    }
}

extern "C" void kernel_launch(void* const* d_in, const int* in_sizes, int n_in,
                              void* d_out, int out_size) {
    (void)in_sizes; (void)n_in; (void)out_size;
    const float* img1 = (const float*)d_in[0];
    const float* img2 = (const float*)d_in[1];
    ssim_main<<<dim3(WI / SW, HI / SEG, 96), 256>>>(img1, img2, (float*)d_out);
}

// round 3
// speedup vs baseline: 1.2253x; 1.0565x over previous
#include <cuda_runtime.h>

// SSIM loss, separable Gaussian 11x11 on fields {s,d,s^2,d^2}, s=x+y, d=x-y.
// Single self-finalizing kernel. Packed f32x2 math, AoS ring, fully unrolled
// chunk loop with compile-time ring-slot folding.

namespace {
constexpr int WI = 512, HI = 512;
constexpr int SW = 64;              // strip width
constexpr int CH = 16;              // rows per produce chunk
constexpr int SEG = 64;             // output rows per block
constexpr int NCH = SEG / CH;       // 4 chunks per block
constexpr int STG2 = 84;            // SD staging row stride (u64 units, 80 used)
constexpr int RW4 = 66;             // ring row stride in float4 (64 used)
constexpr float C1 = 1e-4f;
constexpr float C2 = 9e-4f;
constexpr double NPIX = 25165824.0; // 32*3*512*512
constexpr unsigned NBLK = 8 * 8 * 96; // 6144 blocks
}

__device__ double g_accum;          // zero-init; reset by last block each launch
__device__ unsigned g_done;

using u64 = unsigned long long;

__device__ __forceinline__ u64 pk(float a, float b) {
    u64 r; asm("mov.b64 %0, {%1, %2};" : "=l"(r) : "f"(a), "f"(b)); return r;
}
__device__ __forceinline__ void upk(float& a, float& b, u64 v) {
    asm("mov.b64 {%0, %1}, %2;" : "=f"(a), "=f"(b) : "l"(v));
}
__device__ __forceinline__ u64 ffma2(u64 a, u64 b, u64 c) {
    u64 d; asm("fma.rn.f32x2 %0, %1, %2, %3;" : "=l"(d) : "l"(a), "l"(b), "l"(c));
    return d;
}
__device__ __forceinline__ u64 fmul2(u64 a, u64 b) {
    u64 d; asm("mul.rn.f32x2 %0, %1, %2;" : "=l"(d) : "l"(a), "l"(b));
    return d;
}

__device__ __forceinline__ int SWZ2(int c) { return c ^ ((((c) >> 4) & 1) << 1); } // u64 units
__device__ __forceinline__ int SWZ4(int c) { return c ^ (((c) >> 3) & 7); }        // float4 units

__global__ void __launch_bounds__(256, 4) ssim_main(const float* __restrict__ img1,
                                                    const float* __restrict__ img2,
                                                    float* __restrict__ out)
{
    __shared__ u64 SD[CH][STG2];         // (s,d) packed per px
    __shared__ float4 Ring[32][RW4];     // {S,D,S2,D2} per px
    __shared__ float wsum[8];

    const float Wf[6] = {0.00102838f, 0.00759877f, 0.03600077f,
                         0.10936070f, 0.21300552f, 0.26601174f};
    u64 wp[6];
    #pragma unroll
    for (int i = 0; i < 6; i++) wp[i] = pk(Wf[i], Wf[i]);

    const int tid   = threadIdx.x;
    const int x0    = blockIdx.x * SW;
    const int segY  = blockIdx.y * SEG;
    const int plane = blockIdx.z;
    const float* p1 = img1 + (size_t)plane * (size_t)(WI * HI);
    const float* p2 = img2 + (size_t)plane * (size_t)(WI * HI);

    const int hrow = tid >> 4;           // 0..15
    const int hcg  = tid & 15;           // 0..15 (4 outputs each)
    const int vx   = tid & 63;           // 0..63
    const int vrg  = tid >> 6;           // 0..3  (4 output rows each)
    const int vswz = SWZ4(vx);
    const int vb4  = vrg * 4;            // vertical row-group base (local)

    float acc = 0.f;

    // p is a compile-time constant at every call site (fully unrolled loops).
    auto produce = [&](int p) {
        const int yBase = segY + p * CH - 5;
        // ---- stage 16 rows x 80 px of (s,d), zero-padded ----
        #pragma unroll
        for (int u0 = 0; u0 < 2; u0++) {
            int u = tid + u0 * 256;
            if (u < CH * 20) {
                int r  = u / 20;
                int c4 = u - r * 20;
                int yy = yBase + r;
                int gx = x0 - 8 + c4 * 4;
                float4 a = make_float4(0.f, 0.f, 0.f, 0.f);
                float4 b = make_float4(0.f, 0.f, 0.f, 0.f);
                if ((unsigned)yy < (unsigned)HI && (unsigned)gx < (unsigned)WI) {
                    a = *reinterpret_cast<const float4*>(p1 + (size_t)yy * WI + gx);
                    b = *reinterpret_cast<const float4*>(p2 + (size_t)yy * WI + gx);
                }
                ulonglong2 s0, s1;
                s0.x = pk(a.x + b.x, a.x - b.x);
                s0.y = pk(a.y + b.y, a.y - b.y);
                s1.x = pk(a.z + b.z, a.z - b.z);
                s1.y = pk(a.w + b.w, a.w - b.w);
                int c = c4 * 4;
                *reinterpret_cast<ulonglong2*>(&SD[r][SWZ2(c)])     = s0;
                *reinterpret_cast<ulonglong2*>(&SD[r][SWZ2(c + 2)]) = s1;
            }
        }
        __syncthreads();
        // ---- horizontal conv (packed) into ring ----
        {
            // local ring slot: compile-time p, runtime hrow only
            const int slot = (p * CH + hrow - 5) & 31;
            u64 aSD[4] = {0ull, 0ull, 0ull, 0ull};
            u64 aSQ[4] = {0ull, 0ull, 0ull, 0ull};
            // only staged indices q in [3,16] carry taps -> b = 1..8
            #pragma unroll
            for (int b = 1; b < 9; b++) {
                ulonglong2 v = *reinterpret_cast<const ulonglong2*>(
                    &SD[hrow][SWZ2(hcg * 4 + 2 * b)]);
                #pragma unroll
                for (int e = 0; e < 2; e++) {
                    const int q = 2 * b + e;
                    if (q < 3 || q > 16) continue;
                    const u64 sd = (e == 0) ? v.x : v.y;
                    const u64 sq = fmul2(sd, sd);
                    #pragma unroll
                    for (int o = 0; o < 4; o++) {
                        if (q >= o + 3 && q <= o + 13) {
                            const int t = q - o - 3;
                            const int m = (t < 6) ? t : 10 - t;
                            aSD[o] = ffma2(sd, wp[m], aSD[o]);
                            aSQ[o] = ffma2(sq, wp[m], aSQ[o]);
                        }
                    }
                }
            }
            #pragma unroll
            for (int o = 0; o < 4; o++) {
                ulonglong2 st; st.x = aSD[o]; st.y = aSQ[o];
                *reinterpret_cast<ulonglong2*>(&Ring[slot][SWZ4(hcg * 4 + o)]) = st;
            }
        }
        __syncthreads();
    };

    produce(0);
    #pragma unroll
    for (int k = 0; k < NCH; k++) {
        produce(k + 1);

        // ---- vertical conv (packed) + SSIM for local rows [16k, 16k+16) ----
        u64 aSD[4] = {0ull, 0ull, 0ull, 0ull};
        u64 aSQ[4] = {0ull, 0ull, 0ull, 0ull};
        #pragma unroll
        for (int r = 0; r < 14; r++) {
            // (16k - 5 + r) is compile-time; only vb4 (0,4,8,12) is runtime
            const int slot = (k * CH - 5 + r + vb4 + 32) & 31;
            ulonglong2 v = *reinterpret_cast<const ulonglong2*>(&Ring[slot][vswz]);
            #pragma unroll
            for (int o = 0; o < 4; o++) {
                if (r >= o && r <= o + 10) {
                    const int t = r - o;
                    const int m = (t < 6) ? t : 10 - t;
                    aSD[o] = ffma2(v.x, wp[m], aSD[o]);
                    aSQ[o] = ffma2(v.y, wp[m], aSQ[o]);
                }
            }
        }
        #pragma unroll
        for (int o = 0; o < 4; o++) {
            float mus_sq, mud_sq, es, ed;
            upk(mus_sq, mud_sq, fmul2(aSD[o], aSD[o]));
            upk(es, ed, aSQ[o]);
            const float mu12  = 0.25f * (mus_sq - mud_sq);   // mu1*mu2
            const float musum = 0.5f  * (mus_sq + mud_sq);   // mu1^2+mu2^2
            const float cross = 0.25f * (es - ed);           // conv(x*y)
            const float sqsum = 0.5f  * (es + ed);           // conv(x^2)+conv(y^2)
            const float sigma12 = cross - mu12;
            const float sigsum  = sqsum - musum;
            const float num = (2.f * mu12 + C1) * (2.f * sigma12 + C2);
            const float den = (musum + C1) * (sigsum + C2);
            acc += __fdividef(num, den);
        }
    }

    // ---- block reduction -> one double atomic per block ----
    #pragma unroll
    for (int off = 16; off > 0; off >>= 1)
        acc += __shfl_down_sync(0xffffffffu, acc, off);
    if ((tid & 31) == 0) wsum[tid >> 5] = acc;
    __syncthreads();
    if (tid == 0) {
        float s = 0.f;
        #pragma unroll
        for (int i = 0; i < 8; i++) s += wsum[i];
        atomicAdd(&g_accum, (double)s);
        __threadfence();
        unsigned t = atomicAdd(&g_done, 1u);
        if (t == NBLK - 1) {
            double tot = atomicAdd(&g_accum, 0.0);   // L2-coherent read
            out[0] = (float)(1.0 - tot * (1.0 / NPIX));
            g_accum = 0.0;                            // reset for next launch
            g_done  = 0u;
        }
    }
}

extern "C" void kernel_launch(void* const* d_in, const int* in_sizes, int n_in,
                              void* d_out, int out_size) {
    (void)in_sizes; (void)n_in; (void)out_size;
    const float* img1 = (const float*)d_in[0];
    const float* img2 = (const float*)d_in[1];
    ssim_main<<<dim3(WI / SW, HI / SEG, 96), 256>>>(img1, img2, (float*)d_out);
}